// round 5
// baseline (speedup 1.0000x reference)
#include <cuda_runtime.h>
#include <cuda_bf16.h>
#include <math.h>
#include <stdint.h>

// ---------------------------------------------------------------------------
// Problem constants
// ---------------------------------------------------------------------------
namespace {
constexpr int Bn = 256, Sn = 128, En = 300, Pn = 200, Cn = 3;
constexpr long BS = (long)Bn * Sn;  // 32768
constexpr int EP = 304;             // 300 padded to 16B multiple (8 elems)

// ---- f32 scratch (masks + pool only)
constexpr long OFF_MASK1 = 0;
constexpr long OFF_MASK2 = OFF_MASK1 + BS;
constexpr long OFF_POOL  = OFF_MASK2 + BS;
constexpr long F32_TOTAL = OFF_POOL + (long)Bn * 4 * Pn;

// ---- bf16 activation arena: every tensor is two planes (hi, lo = +PLANE)
constexpr long ACT_CAT  = 0;                        // [2][BS][600]
constexpr long CAT_PL   = 2 * BS * 600;
constexpr long ACT_F    = ACT_CAT + 2 * CAT_PL;     // [2*BS][304] (K padded)
constexpr long F_PL     = 2 * BS * EP;
constexpr long ACT_ATT  = ACT_F + 2 * F_PL;         // [2*B][S][S]
constexpr long ATT_PL   = 2 * BS * Sn;
constexpr long ACT_CATP = ACT_ATT + 2 * ATT_PL;     // [2][BS][400]
constexpr long CATP_PL  = 2 * BS * 2 * Pn;
constexpr long ACT_FA   = ACT_CATP + 2 * CATP_PL;   // [2][BS][200]
constexpr long FA_PL    = 2 * BS * Pn;
constexpr long ACT_SIM  = ACT_FA + 2 * FA_PL;       // [B][S][S]
constexpr long SIM_PL   = BS * Sn;
constexpr long ACT_SMT  = ACT_SIM + 2 * SIM_PL;     // [B][S][S]
constexpr long SMT_PL   = BS * Sn;
constexpr long ACT_V    = ACT_SMT + 2 * SMT_PL;     // [2][BS][400]
constexpr long V_PL     = 2 * BS * 2 * Pn;
constexpr long ACT_TOTAL = ACT_V + 2 * V_PL;

// ---- split weights, bf16 [N][Kpad]; lo plane at +N*Kpad
constexpr long WT_INTRA = 0;                          // 300 x 304
constexpr long WT_PROJ1 = WT_INTRA + 2L * 300 * EP;   // 200 x 600
constexpr long WT_PROJ2 = WT_PROJ1 + 2L * 120000;
constexpr long WT_ATT   = WT_PROJ2 + 2L * 120000;     // 200 x 200
constexpr long WT_CMP1  = WT_ATT + 2L * 40000;        // 400 x 400
constexpr long WT_CMP2  = WT_CMP1 + 2L * 160000;
constexpr long WT_TOTAL = WT_CMP2 + 2L * 160000;

// staging smem (bytes): rows padded to 80B for conflict-free ldmatrix
constexpr int SM_AH = 0;
constexpr int SM_AL = 10240;
constexpr int SM_BH = 20480;
constexpr int SM_BL = 30720;
constexpr int SM_BUF = 40960;
constexpr int SMEM_BYTES = 2 * SM_BUF;  // 80 KB
}  // namespace

__device__ float g_scratch[F32_TOTAL];
__device__ __nv_bfloat16 g_act[ACT_TOTAL];
__device__ __nv_bfloat16 g_wt[WT_TOTAL];

// ---------------------------------------------------------------------------
// helpers
// ---------------------------------------------------------------------------
__device__ __forceinline__ uint32_t smem_u32(const void* p) {
    uint32_t a;
    asm("{ .reg .u64 t; cvta.to.shared.u64 t, %1; cvt.u32.u64 %0, t; }" : "=r"(a) : "l"(p));
    return a;
}
__device__ __forceinline__ void split1(float v, __nv_bfloat16& h, __nv_bfloat16& l) {
    h = __float2bfloat16(v);
    l = __float2bfloat16(v - __bfloat162float(h));
}
__device__ __forceinline__ void cp16(uint32_t dst, const void* src, int bytes) {
    asm volatile("cp.async.cg.shared.global [%0], [%1], 16, %2;"
                 :: "r"(dst), "l"(src), "r"(bytes) : "memory");
}
__device__ __forceinline__ void cp_commit() {
    asm volatile("cp.async.commit_group;" ::: "memory");
}
template <int N>
__device__ __forceinline__ void cp_wait() {
    asm volatile("cp.async.wait_group %0;" :: "n"(N) : "memory");
}
__device__ __forceinline__ void ldm_x4(uint32_t* r, uint32_t addr) {
    asm volatile("ldmatrix.sync.aligned.m8n8.x4.shared.b16 {%0,%1,%2,%3}, [%4];"
                 : "=r"(r[0]), "=r"(r[1]), "=r"(r[2]), "=r"(r[3]) : "r"(addr));
}
__device__ __forceinline__ void ldm_x2(uint32_t* r, uint32_t addr) {
    asm volatile("ldmatrix.sync.aligned.m8n8.x2.shared.b16 {%0,%1}, [%2];"
                 : "=r"(r[0]), "=r"(r[1]) : "r"(addr));
}
__device__ __forceinline__ void mma16816(float* c, const uint32_t* a, const uint32_t* b) {
    asm volatile(
        "mma.sync.aligned.m16n8k16.row.col.f32.bf16.bf16.f32 "
        "{%0,%1,%2,%3}, {%4,%5,%6,%7}, {%8,%9}, {%0,%1,%2,%3};"
        : "+f"(c[0]), "+f"(c[1]), "+f"(c[2]), "+f"(c[3])
        : "r"(a[0]), "r"(a[1]), "r"(a[2]), "r"(a[3]), "r"(b[0]), "r"(b[1]));
}

// ---------------------------------------------------------------------------
// Pipelined HMMA GEMM on pre-split bf16 hi/lo planes (3 MMAs / k-step).
//   C planes (M x Nreal) (+relu/+mask) = A planes @ B^T
//   bMode: 0 = B from g_wt ([N][ldb], k-contig), 1 = B from g_act (k-contig),
//          2 = B from g_act, N-major ([K][ldb], transpose-staged)
//   grid = (ceil(N/128), M/128, batch); 256 threads; dyn smem 80KB.
// ---------------------------------------------------------------------------
__global__ void __launch_bounds__(256, 2)
k_hmma_gemm(long offA, int lda, long sA, long planeA,
            int bMode, long offB, int ldb, long sB, long planeB,
            long offC, int ldc, long sC, long planeC,
            int Nreal, int K,
            int doRelu, int useMask, long offMaskR, long offMaskC) {
    extern __shared__ __align__(16) char smem[];
    const uint32_t sb0 = smem_u32(smem);
    const int tid = threadIdx.x;
    const int lane = tid & 31, wid = tid >> 5;
    const int wm = wid & 1, wn = wid >> 1;  // 2x4 warp grid -> 64x32 per warp
    const int n0 = blockIdx.x * 128, m0 = blockIdx.y * 128, b = blockIdx.z;

    const __nv_bfloat16* Ahi = g_act + offA + (long)b * sA;
    const __nv_bfloat16* Alo = Ahi + planeA;
    const __nv_bfloat16* Bhi = (bMode == 0 ? g_wt : g_act) + offB + (long)b * sB;
    const __nv_bfloat16* Blo = Bhi + planeB;
    __nv_bfloat16* Chi = g_act + offC + (long)b * sC;
    __nv_bfloat16* Clo = Chi + planeC;

    float acc[4][4][4] = {};
    const int crow = tid >> 2, cch = tid & 3;       // cp.async slots (2 per thread)
    const int nN = (tid & 63) * 2, nKb = tid >> 6;  // mode-2 coords
    const int nChunks = (K + 31) >> 5;
    uint32_t pfh[8], pfl[8];

// issue cp.async for A chunk `c` into buffer `bi`
#define ISSUE_A(c, bi)                                                          \
    {                                                                           \
        const int k0 = (c) << 5;                                                \
        _Pragma("unroll") for (int i = 0; i < 2; i++) {                         \
            int row = crow + i * 64;                                            \
            int gk = k0 + cch * 8;                                              \
            int bytes = K - gk;                                                 \
            bytes = bytes < 0 ? 0 : (bytes > 8 ? 8 : bytes);                    \
            bytes *= 2;                                                         \
            long ro = (long)(m0 + row) * lda;                                   \
            uint32_t d = sb0 + (bi)*SM_BUF + (uint32_t)(row * 80 + cch * 16);   \
            cp16(d + SM_AH, Ahi + ro + (bytes ? gk : 0), bytes);                \
            cp16(d + SM_AL, Alo + ro + (bytes ? gk : 0), bytes);                \
        }                                                                       \
    }

// issue cp.async for B chunk `c` (k-contig modes) into buffer `bi`
#define ISSUE_B(c, bi)                                                          \
    {                                                                           \
        const int k0 = (c) << 5;                                                \
        _Pragma("unroll") for (int i = 0; i < 2; i++) {                         \
            int n = crow + i * 64;                                              \
            int gn = n0 + n;                                                    \
            int gk = k0 + cch * 8;                                              \
            int bytes = K - gk;                                                 \
            bytes = bytes < 0 ? 0 : (bytes > 8 ? 8 : bytes);                    \
            bytes *= 2;                                                         \
            if (gn >= Nreal) bytes = 0;                                         \
            long ro = bytes ? (long)gn * ldb + gk : 0;                          \
            uint32_t d = sb0 + (bi)*SM_BUF + (uint32_t)(n * 80 + cch * 16);     \
            cp16(d + SM_BH, Bhi + ro, bytes);                                   \
            cp16(d + SM_BL, Blo + ro, bytes);                                   \
        }                                                                       \
    }

// mode-2: LDG B chunk `c` (N-major) into registers
#define LDGB(c)                                                                 \
    {                                                                           \
        const int k0 = (c) << 5;                                                \
        const int gn = n0 + nN;                                                 \
        const bool nin = (gn < Nreal);                                          \
        _Pragma("unroll") for (int it = 0; it < 8; it++) {                      \
            int gk = k0 + nKb + it * 4;                                         \
            if (nin && gk < K) {                                                \
                long e = (long)gk * ldb + gn;                                   \
                pfh[it] = *reinterpret_cast<const uint32_t*>(Bhi + e);          \
                pfl[it] = *reinterpret_cast<const uint32_t*>(Blo + e);          \
            } else {                                                            \
                pfh[it] = 0; pfl[it] = 0;                                       \
            }                                                                   \
        }                                                                       \
    }

// mode-2: scatter registers into smem buffer `bi` (transpose)
#define STOREB(bi)                                                              \
    {                                                                           \
        char* sm = smem + (bi)*SM_BUF;                                          \
        _Pragma("unroll") for (int it = 0; it < 8; it++) {                      \
            int kk = nKb + it * 4;                                              \
            __nv_bfloat162 h2 = *reinterpret_cast<__nv_bfloat162*>(&pfh[it]);   \
            __nv_bfloat162 l2 = *reinterpret_cast<__nv_bfloat162*>(&pfl[it]);   \
            *reinterpret_cast<__nv_bfloat16*>(sm + SM_BH + nN * 80 + kk * 2) = h2.x; \
            *reinterpret_cast<__nv_bfloat16*>(sm + SM_BL + nN * 80 + kk * 2) = l2.x; \
            *reinterpret_cast<__nv_bfloat16*>(sm + SM_BH + (nN + 1) * 80 + kk * 2) = h2.y; \
            *reinterpret_cast<__nv_bfloat16*>(sm + SM_BL + (nN + 1) * 80 + kk * 2) = l2.y; \
        }                                                                       \
    }

    // prologue: chunk 0
    ISSUE_A(0, 0);
    if (bMode < 2) { ISSUE_B(0, 0); } else { LDGB(0); }
    cp_commit();
    if (bMode == 2) STOREB(0);

    for (int c = 0; c < nChunks; c++) {
        const bool more = (c + 1 < nChunks);
        if (more) {
            ISSUE_A(c + 1, (c + 1) & 1);
            if (bMode < 2) ISSUE_B(c + 1, (c + 1) & 1);
            cp_commit();
            if (bMode == 2) LDGB(c + 1);
        }
        if (more) cp_wait<1>(); else cp_wait<0>();
        __syncthreads();

        // ---- compute on buffer c&1: 2 k-steps of 16
        const uint32_t sb = sb0 + (uint32_t)((c & 1) * SM_BUF);
#pragma unroll
        for (int ks = 0; ks < 2; ks++) {
            uint32_t bh[4][2], bl[4][2];
#pragma unroll
            for (int ni = 0; ni < 4; ni++) {
                uint32_t off = (uint32_t)((wn * 32 + ni * 8 + (lane & 7)) * 80 + ks * 32 +
                                          ((lane >> 3) & 1) * 16);
                ldm_x2(bh[ni], sb + SM_BH + off);
                ldm_x2(bl[ni], sb + SM_BL + off);
            }
#pragma unroll
            for (int mi = 0; mi < 4; mi++) {
                uint32_t ah[4], al[4];
                uint32_t off = (uint32_t)((wm * 64 + mi * 16 + (lane & 15)) * 80 + ks * 32 +
                                          (lane >> 4) * 16);
                ldm_x4(ah, sb + SM_AH + off);
                ldm_x4(al, sb + SM_AL + off);
#pragma unroll
                for (int ni = 0; ni < 4; ni++) {
                    mma16816(acc[mi][ni], ah, bh[ni]);
                    mma16816(acc[mi][ni], ah, bl[ni]);
                    mma16816(acc[mi][ni], al, bh[ni]);
                }
            }
        }
        if (bMode == 2 && more) STOREB((c + 1) & 1);
        __syncthreads();
    }
#undef ISSUE_A
#undef ISSUE_B
#undef LDGB
#undef STOREB

    // ---- epilogue: relu / mask, split to hi/lo planes
    const float* mR = g_scratch + offMaskR + (long)b * Sn;
    const float* mC = g_scratch + offMaskC + (long)b * Sn;
    const int trow = lane >> 2, tcol = (lane & 3) * 2;
#pragma unroll
    for (int mi = 0; mi < 4; mi++) {
        int r0 = m0 + wm * 64 + mi * 16 + trow;
        float rm0 = useMask ? mR[r0 - m0 + 0] : 1.0f;  // masks only when M==Sn
        float rm1 = useMask ? mR[r0 - m0 + 8] : 1.0f;
#pragma unroll
        for (int ni = 0; ni < 4; ni++) {
            int c0 = n0 + wn * 32 + ni * 8 + tcol;
            if (c0 >= Nreal) continue;
            float v0 = acc[mi][ni][0], v1 = acc[mi][ni][1];
            float v2 = acc[mi][ni][2], v3 = acc[mi][ni][3];
            if (doRelu) {
                v0 = fmaxf(v0, 0.f); v1 = fmaxf(v1, 0.f);
                v2 = fmaxf(v2, 0.f); v3 = fmaxf(v3, 0.f);
            }
            if (useMask) {
                float cm0 = mC[c0], cm1 = mC[c0 + 1];
                v0 *= rm0 * cm0; v1 *= rm0 * cm1;
                v2 *= rm1 * cm0; v3 *= rm1 * cm1;
            }
            __nv_bfloat162 h01, l01, h23, l23;
            split1(v0, h01.x, l01.x); split1(v1, h01.y, l01.y);
            split1(v2, h23.x, l23.x); split1(v3, h23.y, l23.y);
            long e0 = (long)r0 * ldc + c0, e1 = (long)(r0 + 8) * ldc + c0;
            *reinterpret_cast<__nv_bfloat162*>(Chi + e0) = h01;
            *reinterpret_cast<__nv_bfloat162*>(Clo + e0) = l01;
            *reinterpret_cast<__nv_bfloat162*>(Chi + e1) = h23;
            *reinterpret_cast<__nv_bfloat162*>(Clo + e1) = l23;
        }
    }
}

// ---------------------------------------------------------------------------
// All weights: transpose + split, one launch. W [K][N] f32 -> [N][Kp] hi/lo
// ---------------------------------------------------------------------------
__global__ void k_wsplit_all(const float* __restrict__ w_intra,
                             const float* __restrict__ w_proj1,
                             const float* __restrict__ w_proj2,
                             const float* __restrict__ w_att,
                             const float* __restrict__ w_cmp1,
                             const float* __restrict__ w_cmp2) {
    const float* W;
    int K, N, Kp;
    long off;
    switch (blockIdx.y) {
        case 0: W = w_intra; K = En;     N = En;     Kp = EP;     off = WT_INTRA; break;
        case 1: W = w_proj1; K = 2 * En; N = Pn;     Kp = 2 * En; off = WT_PROJ1; break;
        case 2: W = w_proj2; K = 2 * En; N = Pn;     Kp = 2 * En; off = WT_PROJ2; break;
        case 3: W = w_att;   K = Pn;     N = Pn;     Kp = Pn;     off = WT_ATT;   break;
        case 4: W = w_cmp1;  K = 2 * Pn; N = 2 * Pn; Kp = 2 * Pn; off = WT_CMP1;  break;
        default: W = w_cmp2; K = 2 * Pn; N = 2 * Pn; Kp = 2 * Pn; off = WT_CMP2;  break;
    }
    long total = (long)K * N;
    long plane = (long)N * Kp;
    for (long i = (long)blockIdx.x * blockDim.x + threadIdx.x; i < total;
         i += (long)gridDim.x * blockDim.x) {
        int n = (int)(i / K), k = (int)(i % K);
        float v = W[(long)k * N + n];
        __nv_bfloat16 h, l;
        split1(v, h, l);
        g_wt[off + (long)n * Kp + k] = h;
        g_wt[off + plane + (long)n * Kp + k] = l;
    }
}

// ---------------------------------------------------------------------------
// Non-GEMM kernels (plane-aware)
// ---------------------------------------------------------------------------
__global__ void k_seqmask(const int* __restrict__ x1, const int* __restrict__ x2) {
    int b = blockIdx.x;
    const int* x = blockIdx.y ? x2 : x1;
    float* m = g_scratch + (blockIdx.y ? OFF_MASK2 : OFF_MASK1);
    int t = threadIdx.x;
    int nz = __syncthreads_count(x[b * Sn + t] != 0);
    m[b * Sn + t] = (t < nz) ? 1.0f : 0.0f;
}

__global__ void k_gather(const int* __restrict__ x1, const int* __restrict__ x2,
                         const float* __restrict__ emb) {
    long bs = blockIdx.x;
    int side = blockIdx.y;
    const int* x = side ? x2 : x1;
    int row = x[bs];
    const float* e = emb + (long)row * En;
    int t = threadIdx.x;
    float v[3];
    float ss = 0.f;
#pragma unroll
    for (int i = 0; i < 3; i++) {
        int idx = t + i * 128;
        v[i] = (idx < En) ? e[idx] : 0.f;
        ss += v[i] * v[i];
    }
    __shared__ float red[4];
#pragma unroll
    for (int o = 16; o; o >>= 1) ss += __shfl_xor_sync(0xffffffffu, ss, o);
    if ((t & 31) == 0) red[t >> 5] = ss;
    __syncthreads();
    float inv = 1.0f / sqrtf(fmaxf(red[0] + red[1] + red[2] + red[3], 1e-12f));
    __nv_bfloat16* hi = g_act + ACT_CAT + (long)side * BS * 600 + bs * 600;
    __nv_bfloat16* lo = hi + CAT_PL;
#pragma unroll
    for (int i = 0; i < 3; i++) {
        int idx = t + i * 128;
        if (idx < En) {
            __nv_bfloat16 h, l;
            split1(v[i] * inv, h, l);
            hi[idx] = h;
            lo[idx] = l;
        }
    }
}

// row softmax over S=128, on hi/lo planes, in place; optional distance bias
__global__ void k_softmax_rows(long off, long plane, const float* __restrict__ biasPtr,
                               int useDbias) {
    long bi = blockIdx.x;
    int i = (int)(bi % Sn);
    __nv_bfloat16* hi = g_act + off + bi * Sn;
    __nv_bfloat16* lo = hi + plane;
    int j = threadIdx.x;
    float v = __bfloat162float(hi[j]) + __bfloat162float(lo[j]);
    if (useDbias) {
        int d = i - j; if (d < 0) d = -d;
        if (d >= 10) v += biasPtr[0];
    }
    __shared__ float shm[4], shs[4];
    float m = v;
#pragma unroll
    for (int o = 16; o; o >>= 1) m = fmaxf(m, __shfl_xor_sync(0xffffffffu, m, o));
    if ((j & 31) == 0) shm[j >> 5] = m;
    __syncthreads();
    m = fmaxf(fmaxf(shm[0], shm[1]), fmaxf(shm[2], shm[3]));
    float e = expf(v - m);
    float s = e;
#pragma unroll
    for (int o = 16; o; o >>= 1) s += __shfl_xor_sync(0xffffffffu, s, o);
    if ((j & 31) == 0) shs[j >> 5] = s;
    __syncthreads();
    s = shs[0] + shs[1] + shs[2] + shs[3];
    __nv_bfloat16 h, l;
    split1(e / s, h, l);
    hi[j] = h;
    lo[j] = l;
}

// column softmax written transposed: out[b,j,k] = softmax_k(sim[b,k,j])
__global__ void k_softmax_colsT(long offSim, long plSim, long offOut, long plOut) {
    int b = blockIdx.x;
    int j0 = blockIdx.y * 32;
    __shared__ float sh[128][33];
    __shared__ float cmax[32], cinv[32];
    const __nv_bfloat16* simH = g_act + offSim + (long)b * Sn * Sn;
    const __nv_bfloat16* simL = simH + plSim;
    __nv_bfloat16* outH = g_act + offOut + (long)b * Sn * Sn;
    __nv_bfloat16* outL = outH + plOut;
    int tid = threadIdx.x;
    for (int idx = tid; idx < 128 * 32; idx += 256) {
        int k = idx >> 5, j = idx & 31;
        long e = (long)k * Sn + j0 + j;
        sh[k][j] = __bfloat162float(simH[e]) + __bfloat162float(simL[e]);
    }
    __syncthreads();
    if (tid < 32) {
        float m = -1e30f;
        for (int k = 0; k < 128; k++) m = fmaxf(m, sh[k][tid]);
        float s = 0.f;
        for (int k = 0; k < 128; k++) s += expf(sh[k][tid] - m);
        cmax[tid] = m;
        cinv[tid] = 1.0f / s;
    }
    __syncthreads();
    for (int idx = tid; idx < 128 * 32; idx += 256) {
        int j = idx >> 7, k = idx & 127;
        __nv_bfloat16 h, l;
        split1(expf(sh[k][j] - cmax[j]) * cinv[j], h, l);
        long e = (long)(j0 + j) * Sn + k;
        outH[e] = h;
        outL[e] = l;
    }
}

__global__ void k_pool() {
    int b = blockIdx.x;
    __shared__ float m1[128], m2[128];
    int tid = threadIdx.x;
    if (tid < 128) {
        m1[tid] = g_scratch[OFF_MASK1 + (long)b * Sn + tid];
        m2[tid] = g_scratch[OFF_MASK2 + (long)b * Sn + tid];
    }
    __syncthreads();
    const __nv_bfloat16* v1h = g_act + ACT_V + (long)b * Sn * 400;
    const __nv_bfloat16* v2h = v1h + BS * 400;  // side 2 offset within hi plane
    float* pool = g_scratch + OFF_POOL + (long)b * 800;
    for (int n = tid; n < 400; n += 256) {
        float s1 = 0.f, s2 = 0.f;
        for (int s = 0; s < 128; s++) {
            long e = (long)s * 400 + n;
            s1 += (__bfloat162float(v1h[e]) + __bfloat162float(v1h[V_PL + e])) * m1[s];
            s2 += (__bfloat162float(v2h[e]) + __bfloat162float(v2h[V_PL + e])) * m2[s];
        }
        pool[n] = s1;
        pool[400 + n] = s2;
    }
}

__global__ void k_final(const float* __restrict__ w_agg, float* __restrict__ out) {
    int b = blockIdx.x;
    int tid = threadIdx.x;
    int c = tid >> 5, lane = tid & 31;
    const float* p = g_scratch + OFF_POOL + (long)b * 800;
    float acc = 0.f;
    for (int n = lane; n < 800; n += 32) acc += p[n] * w_agg[n * Cn + c];
#pragma unroll
    for (int o = 16; o; o >>= 1) acc += __shfl_xor_sync(0xffffffffu, acc, o);
    if (lane == 0) out[b * Cn + c] = fmaxf(acc, 0.f);
}

// ---------------------------------------------------------------------------
// Orchestration
// ---------------------------------------------------------------------------
static inline void launch_gemm(long offA, int lda, long sA, long planeA,
                               int bMode, long offB, int ldb, long sB, long planeB,
                               long offC, int ldc, long sC, long planeC,
                               int M, int Nreal, int K,
                               int doRelu, int useMask, long offMaskR, long offMaskC,
                               int batch) {
    dim3 grid((Nreal + 127) / 128, M / 128, batch);
    k_hmma_gemm<<<grid, 256, SMEM_BYTES>>>(offA, lda, sA, planeA,
                                           bMode, offB, ldb, sB, planeB,
                                           offC, ldc, sC, planeC, Nreal, K,
                                           doRelu, useMask, offMaskR, offMaskC);
}

extern "C" void kernel_launch(void* const* d_in, const int* in_sizes, int n_in,
                              void* d_out, int out_size) {
    const int* x1 = (const int*)d_in[0];
    const int* x2 = (const int*)d_in[1];
    const float* emb = (const float*)d_in[2];
    const float* w_intra = (const float*)d_in[3];
    const float* bias_intra = (const float*)d_in[4];
    const float* w_proj1 = (const float*)d_in[5];
    const float* w_proj2 = (const float*)d_in[6];
    const float* w_att = (const float*)d_in[7];
    const float* w_cmp1 = (const float*)d_in[8];
    const float* w_cmp2 = (const float*)d_in[9];
    const float* w_agg = (const float*)d_in[10];
    float* out = (float*)d_out;

    cudaFuncSetAttribute(k_hmma_gemm, cudaFuncAttributeMaxDynamicSharedMemorySize, SMEM_BYTES);

    k_seqmask<<<dim3(Bn, 2), Sn>>>(x1, x2);
    k_gather<<<dim3((unsigned)BS, 2), 128>>>(x1, x2, emb);
    k_wsplit_all<<<dim3(160, 6), 256>>>(w_intra, w_proj1, w_proj2, w_att, w_cmp1, w_cmp2);

    // f = relu(e @ w_intra), both sides: [2 x BS x 300], K=300
    launch_gemm(ACT_CAT, 600, BS * 600, CAT_PL,
                0, WT_INTRA, EP, 0, 300L * EP,
                ACT_F, EP, BS * EP, F_PL,
                (int)BS, En, En, 1, 0, 0, 0, 2);

    // att[g] = f[g] @ f[g]^T, 512 batches: [128x128], K=300
    launch_gemm(ACT_F, EP, (long)Sn * EP, F_PL,
                1, ACT_F, EP, (long)Sn * EP, F_PL,
                ACT_ATT, Sn, (long)Sn * Sn, ATT_PL,
                Sn, Sn, En, 0, 0, 0, 0, 2 * Bn);

    k_softmax_rows<<<(unsigned)(2 * BS), Sn>>>(ACT_ATT, ATT_PL, bias_intra, 1);

    // xp[g] = att[g] @ e[g]: B N-major from cat cols 0:300 -> cat cols 300:600
    launch_gemm(ACT_ATT, Sn, (long)Sn * Sn, ATT_PL,
                2, ACT_CAT, 600, (long)Sn * 600, CAT_PL,
                ACT_CAT + En, 600, (long)Sn * 600, CAT_PL,
                Sn, En, Sn, 0, 0, 0, 0, 2 * Bn);

    // x_proj = relu(cat @ w_proj{1,2}): [2 x BS x 200], K=600
    launch_gemm(ACT_CAT, 600, BS * 600, CAT_PL,
                0, WT_PROJ1, 600, WT_PROJ2 - WT_PROJ1, 120000,
                ACT_CATP, 400, BS * 400, CATP_PL,
                (int)BS, Pn, 2 * En, 1, 0, 0, 0, 2);

    // fa = relu(x_proj @ w_att): [2 x BS x 200], K=200
    launch_gemm(ACT_CATP, 400, BS * 400, CATP_PL,
                0, WT_ATT, Pn, 0, 40000,
                ACT_FA, Pn, BS * Pn, FA_PL,
                (int)BS, Pn, Pn, 1, 0, 0, 0, 2);

    // sim[b] = fa1[b] @ fa2[b]^T, multiplicative mask epilogue
    launch_gemm(ACT_FA, Pn, (long)Sn * Pn, FA_PL,
                1, ACT_FA + BS * Pn, Pn, (long)Sn * Pn, FA_PL,
                ACT_SIM, Sn, (long)Sn * Sn, SIM_PL,
                Sn, Sn, Pn, 0, 1, OFF_MASK1, OFF_MASK2, Bn);

    k_softmax_colsT<<<dim3(Bn, 4), 256>>>(ACT_SIM, SIM_PL, ACT_SMT, SMT_PL);
    k_softmax_rows<<<(unsigned)BS, Sn>>>(ACT_SIM, SIM_PL, nullptr, 0);

    // beta[b] = sm2[b] @ x2p[b]: B N-major from catp side2 -> cat1p cols 200:400
    launch_gemm(ACT_SIM, Sn, (long)Sn * Sn, SIM_PL,
                2, ACT_CATP + BS * 400, 400, (long)Sn * 400, CATP_PL,
                ACT_CATP + Pn, 400, (long)Sn * 400, CATP_PL,
                Sn, Pn, Sn, 0, 0, 0, 0, Bn);

    // alpha[b] = smT[b] @ x1p[b] -> cat2p cols 200:400
    launch_gemm(ACT_SMT, Sn, (long)Sn * Sn, SMT_PL,
                2, ACT_CATP, 400, (long)Sn * 400, CATP_PL,
                ACT_CATP + BS * 400 + Pn, 400, (long)Sn * 400, CATP_PL,
                Sn, Pn, Sn, 0, 0, 0, 0, Bn);

    // v = relu([xp|attend] @ w_cmp{1,2}): [2 x BS x 400], K=400
    launch_gemm(ACT_CATP, 400, BS * 400, CATP_PL,
                0, WT_CMP1, 2 * Pn, WT_CMP2 - WT_CMP1, 160000,
                ACT_V, 400, BS * 400, V_PL,
                (int)BS, 2 * Pn, 2 * Pn, 1, 0, 0, 0, 2);

    k_pool<<<Bn, 256>>>();
    k_final<<<Bn, 96>>>(w_agg, out);
}

// round 6
// speedup vs baseline: 1.1539x; 1.1539x over previous
#include <cuda_runtime.h>
#include <cuda_bf16.h>
#include <math.h>
#include <stdint.h>

// ---------------------------------------------------------------------------
// Problem constants
// ---------------------------------------------------------------------------
namespace {
constexpr int Bn = 256, Sn = 128, En = 300, Pn = 200, Cn = 3;
constexpr long BS = (long)Bn * Sn;  // 32768
constexpr int EP = 304;             // 300 padded to 16B multiple

// ---- f32 scratch (masks + pool)
constexpr long OFF_MASK1 = 0;
constexpr long OFF_MASK2 = OFF_MASK1 + BS;
constexpr long OFF_POOL  = OFF_MASK2 + BS;
constexpr long F32_TOTAL = OFF_POOL + (long)Bn * 4 * Pn;

// ---- bf16 activation arena: every tensor is two planes (hi, lo = +PLANE)
constexpr long ACT_CAT  = 0;                        // [2][BS][600]
constexpr long CAT_PL   = 2 * BS * 600;
constexpr long ACT_F    = ACT_CAT + 2 * CAT_PL;     // [2*BS][304]
constexpr long F_PL     = 2 * BS * EP;
constexpr long ACT_ATT  = ACT_F + 2 * F_PL;         // [2*B][S][S] (softmaxed)
constexpr long ATT_PL   = 2 * BS * Sn;
constexpr long ACT_CATP = ACT_ATT + 2 * ATT_PL;     // [2][BS][400]
constexpr long CATP_PL  = 2 * BS * 2 * Pn;
constexpr long ACT_FA   = ACT_CATP + 2 * CATP_PL;   // [2][BS][200]
constexpr long FA_PL    = 2 * BS * Pn;
constexpr long ACT_SIM  = ACT_FA + 2 * FA_PL;       // [B][S][S] row-softmaxed
constexpr long SIM_PL   = BS * Sn;
constexpr long ACT_SMT  = ACT_SIM + 2 * SIM_PL;     // [B][S][S] col-softmax^T
constexpr long SMT_PL   = BS * Sn;
constexpr long ACT_TOTAL = ACT_SMT + 2 * SMT_PL;

// ---- split weights, bf16 [N][Kpad]; lo plane at +N*Kpad
constexpr long WT_INTRA = 0;                          // 300 x 304
constexpr long WT_PROJ1 = WT_INTRA + 2L * 300 * EP;   // 200 x 600
constexpr long WT_PROJ2 = WT_PROJ1 + 2L * 120000;
constexpr long WT_ATT   = WT_PROJ2 + 2L * 120000;     // 200 x 200
constexpr long WT_CMP1  = WT_ATT + 2L * 40000;        // 400 x 400
constexpr long WT_CMP2  = WT_CMP1 + 2L * 160000;
constexpr long WT_TOTAL = WT_CMP2 + 2L * 160000;

// staging smem (bytes): rows padded to 80B for conflict-free ldmatrix
constexpr int SM_AH = 0;
constexpr int SM_AL = 10240;
constexpr int SM_BH = 20480;
constexpr int SM_BL = 30720;
constexpr int SM_BUF = 40960;
constexpr int SMEM_BYTES = 2 * SM_BUF;  // 80 KB (also covers 128x129 f32)

enum { EPI_STORE = 0, EPI_ATT = 1, EPI_SIM = 2, EPI_POOL = 3 };
}  // namespace

__device__ float g_scratch[F32_TOTAL];
__device__ __nv_bfloat16 g_act[ACT_TOTAL];
__device__ __nv_bfloat16 g_wt[WT_TOTAL];

// ---------------------------------------------------------------------------
// helpers
// ---------------------------------------------------------------------------
__device__ __forceinline__ uint32_t smem_u32(const void* p) {
    uint32_t a;
    asm("{ .reg .u64 t; cvta.to.shared.u64 t, %1; cvt.u32.u64 %0, t; }" : "=r"(a) : "l"(p));
    return a;
}
__device__ __forceinline__ void split1(float v, __nv_bfloat16& h, __nv_bfloat16& l) {
    h = __float2bfloat16(v);
    l = __float2bfloat16(v - __bfloat162float(h));
}
__device__ __forceinline__ void cp16(uint32_t dst, const void* src, int bytes) {
    asm volatile("cp.async.cg.shared.global [%0], [%1], 16, %2;"
                 :: "r"(dst), "l"(src), "r"(bytes) : "memory");
}
__device__ __forceinline__ void cp_commit() {
    asm volatile("cp.async.commit_group;" ::: "memory");
}
template <int N>
__device__ __forceinline__ void cp_wait() {
    asm volatile("cp.async.wait_group %0;" :: "n"(N) : "memory");
}
__device__ __forceinline__ void ldm_x4(uint32_t* r, uint32_t addr) {
    asm volatile("ldmatrix.sync.aligned.m8n8.x4.shared.b16 {%0,%1,%2,%3}, [%4];"
                 : "=r"(r[0]), "=r"(r[1]), "=r"(r[2]), "=r"(r[3]) : "r"(addr));
}
__device__ __forceinline__ void ldm_x2(uint32_t* r, uint32_t addr) {
    asm volatile("ldmatrix.sync.aligned.m8n8.x2.shared.b16 {%0,%1}, [%2];"
                 : "=r"(r[0]), "=r"(r[1]) : "r"(addr));
}
__device__ __forceinline__ void mma16816(float* c, const uint32_t* a, const uint32_t* b) {
    asm volatile(
        "mma.sync.aligned.m16n8k16.row.col.f32.bf16.bf16.f32 "
        "{%0,%1,%2,%3}, {%4,%5,%6,%7}, {%8,%9}, {%0,%1,%2,%3};"
        : "+f"(c[0]), "+f"(c[1]), "+f"(c[2]), "+f"(c[3])
        : "r"(a[0]), "r"(a[1]), "r"(a[2]), "r"(a[3]), "r"(b[0]), "r"(b[1]));
}

// ---------------------------------------------------------------------------
// Pipelined HMMA GEMM on pre-split bf16 hi/lo planes (3 MMAs / k-step),
// with fused epilogues:
//   EPI_STORE: (+relu) -> hi/lo planes at offC
//   EPI_ATT:   +dbias, row softmax (in-CTA over 128x128) -> planes at offC
//   EPI_SIM:   x mask1[r]*mask2[c], row softmax -> offC, col softmax^T -> offC2
//   EPI_POOL:  relu, masked sum over rows -> f32 pool (g_scratch)
// bMode: 0 = B from g_wt ([N][ldb] k-contig), 1 = B from g_act (k-contig),
//        2 = B from g_act N-major ([K][ldb], transpose-staged)
// ---------------------------------------------------------------------------
template <int EPI>
__global__ void __launch_bounds__(256, 2)
k_hmma_gemm(long offA, int lda, long sA, long planeA,
            int bMode, long offB, int ldb, long sB, long planeB,
            long offC, int ldc, long sC, long planeC,
            long offC2, long planeC2,
            int Nreal, int K, int doRelu, const float* biasPtr) {
    extern __shared__ __align__(16) char smem[];
    const uint32_t sb0 = smem_u32(smem);
    const int tid = threadIdx.x;
    const int lane = tid & 31, wid = tid >> 5;
    const int wm = wid & 1, wn = wid >> 1;  // 2x4 warp grid -> 64x32 per warp
    const int n0 = blockIdx.x * 128, m0 = blockIdx.y * 128, b = blockIdx.z;

    const __nv_bfloat16* Ahi = g_act + offA + (long)b * sA;
    const __nv_bfloat16* Alo = Ahi + planeA;
    const __nv_bfloat16* Bhi = (bMode == 0 ? g_wt : g_act) + offB + (long)b * sB;
    const __nv_bfloat16* Blo = Bhi + planeB;

    float acc[4][4][4] = {};
    const int crow = tid >> 2, cch = tid & 3;
    const int nN = (tid & 63) * 2, nKb = tid >> 6;
    const int nChunks = (K + 31) >> 5;
    uint32_t pfh[8], pfl[8];

#define ISSUE_A(c, bi)                                                          \
    {                                                                           \
        const int k0 = (c) << 5;                                                \
        _Pragma("unroll") for (int i = 0; i < 2; i++) {                         \
            int row = crow + i * 64;                                            \
            int gk = k0 + cch * 8;                                              \
            int bytes = K - gk;                                                 \
            bytes = bytes < 0 ? 0 : (bytes > 8 ? 8 : bytes);                    \
            bytes *= 2;                                                         \
            long ro = (long)(m0 + row) * lda;                                   \
            uint32_t d = sb0 + (bi)*SM_BUF + (uint32_t)(row * 80 + cch * 16);   \
            cp16(d + SM_AH, Ahi + ro + (bytes ? gk : 0), bytes);                \
            cp16(d + SM_AL, Alo + ro + (bytes ? gk : 0), bytes);                \
        }                                                                       \
    }
#define ISSUE_B(c, bi)                                                          \
    {                                                                           \
        const int k0 = (c) << 5;                                                \
        _Pragma("unroll") for (int i = 0; i < 2; i++) {                         \
            int n = crow + i * 64;                                              \
            int gn = n0 + n;                                                    \
            int gk = k0 + cch * 8;                                              \
            int bytes = K - gk;                                                 \
            bytes = bytes < 0 ? 0 : (bytes > 8 ? 8 : bytes);                    \
            bytes *= 2;                                                         \
            if (gn >= Nreal) bytes = 0;                                         \
            long ro = bytes ? (long)gn * ldb + gk : 0;                          \
            uint32_t d = sb0 + (bi)*SM_BUF + (uint32_t)(n * 80 + cch * 16);     \
            cp16(d + SM_BH, Bhi + ro, bytes);                                   \
            cp16(d + SM_BL, Blo + ro, bytes);                                   \
        }                                                                       \
    }
#define LDGB(c)                                                                 \
    {                                                                           \
        const int k0 = (c) << 5;                                                \
        const int gn = n0 + nN;                                                 \
        const bool nin = (gn < Nreal);                                          \
        _Pragma("unroll") for (int it = 0; it < 8; it++) {                      \
            int gk = k0 + nKb + it * 4;                                         \
            if (nin && gk < K) {                                                \
                long e = (long)gk * ldb + gn;                                   \
                pfh[it] = *reinterpret_cast<const uint32_t*>(Bhi + e);          \
                pfl[it] = *reinterpret_cast<const uint32_t*>(Blo + e);          \
            } else {                                                            \
                pfh[it] = 0; pfl[it] = 0;                                       \
            }                                                                   \
        }                                                                       \
    }
#define STOREB(bi)                                                              \
    {                                                                           \
        char* sm = smem + (bi)*SM_BUF;                                          \
        _Pragma("unroll") for (int it = 0; it < 8; it++) {                      \
            int kk = nKb + it * 4;                                              \
            __nv_bfloat162 h2 = *reinterpret_cast<__nv_bfloat162*>(&pfh[it]);   \
            __nv_bfloat162 l2 = *reinterpret_cast<__nv_bfloat162*>(&pfl[it]);   \
            *reinterpret_cast<__nv_bfloat16*>(sm + SM_BH + nN * 80 + kk * 2) = h2.x; \
            *reinterpret_cast<__nv_bfloat16*>(sm + SM_BL + nN * 80 + kk * 2) = l2.x; \
            *reinterpret_cast<__nv_bfloat16*>(sm + SM_BH + (nN + 1) * 80 + kk * 2) = h2.y; \
            *reinterpret_cast<__nv_bfloat16*>(sm + SM_BL + (nN + 1) * 80 + kk * 2) = l2.y; \
        }                                                                       \
    }

    ISSUE_A(0, 0);
    if (bMode < 2) { ISSUE_B(0, 0); } else { LDGB(0); }
    cp_commit();
    if (bMode == 2) STOREB(0);

    for (int c = 0; c < nChunks; c++) {
        const bool more = (c + 1 < nChunks);
        if (more) {
            ISSUE_A(c + 1, (c + 1) & 1);
            if (bMode < 2) ISSUE_B(c + 1, (c + 1) & 1);
            cp_commit();
            if (bMode == 2) LDGB(c + 1);
        }
        if (more) cp_wait<1>(); else cp_wait<0>();
        __syncthreads();

        const uint32_t sb = sb0 + (uint32_t)((c & 1) * SM_BUF);
#pragma unroll
        for (int ks = 0; ks < 2; ks++) {
            uint32_t bh[4][2], bl[4][2];
#pragma unroll
            for (int ni = 0; ni < 4; ni++) {
                uint32_t off = (uint32_t)((wn * 32 + ni * 8 + (lane & 7)) * 80 + ks * 32 +
                                          ((lane >> 3) & 1) * 16);
                ldm_x2(bh[ni], sb + SM_BH + off);
                ldm_x2(bl[ni], sb + SM_BL + off);
            }
#pragma unroll
            for (int mi = 0; mi < 4; mi++) {
                uint32_t ah[4], al[4];
                uint32_t off = (uint32_t)((wm * 64 + mi * 16 + (lane & 15)) * 80 + ks * 32 +
                                          (lane >> 4) * 16);
                ldm_x4(ah, sb + SM_AH + off);
                ldm_x4(al, sb + SM_AL + off);
#pragma unroll
                for (int ni = 0; ni < 4; ni++) {
                    mma16816(acc[mi][ni], ah, bh[ni]);
                    mma16816(acc[mi][ni], ah, bl[ni]);
                    mma16816(acc[mi][ni], al, bh[ni]);
                }
            }
        }
        if (bMode == 2 && more) STOREB((c + 1) & 1);
        __syncthreads();
    }
#undef ISSUE_A
#undef ISSUE_B
#undef LDGB
#undef STOREB

    const int trow = lane >> 2, tcol = (lane & 3) * 2;

    if constexpr (EPI == EPI_STORE) {
        __nv_bfloat16* Chi = g_act + offC + (long)b * sC;
        __nv_bfloat16* Clo = Chi + planeC;
#pragma unroll
        for (int mi = 0; mi < 4; mi++) {
            int r0 = m0 + wm * 64 + mi * 16 + trow;
#pragma unroll
            for (int ni = 0; ni < 4; ni++) {
                int c0 = n0 + wn * 32 + ni * 8 + tcol;
                if (c0 >= Nreal) continue;
                float v0 = acc[mi][ni][0], v1 = acc[mi][ni][1];
                float v2 = acc[mi][ni][2], v3 = acc[mi][ni][3];
                if (doRelu) {
                    v0 = fmaxf(v0, 0.f); v1 = fmaxf(v1, 0.f);
                    v2 = fmaxf(v2, 0.f); v3 = fmaxf(v3, 0.f);
                }
                __nv_bfloat162 h01, l01, h23, l23;
                split1(v0, h01.x, l01.x); split1(v1, h01.y, l01.y);
                split1(v2, h23.x, l23.x); split1(v3, h23.y, l23.y);
                long e0 = (long)r0 * ldc + c0, e1 = (long)(r0 + 8) * ldc + c0;
                *reinterpret_cast<__nv_bfloat162*>(Chi + e0) = h01;
                *reinterpret_cast<__nv_bfloat162*>(Clo + e0) = l01;
                *reinterpret_cast<__nv_bfloat162*>(Chi + e1) = h23;
                *reinterpret_cast<__nv_bfloat162*>(Clo + e1) = l23;
            }
        }
    } else if constexpr (EPI == EPI_ATT || EPI == EPI_SIM) {
        // dump acc (+dbias or masks) into 128x129 f32 smem
        float* smF = reinterpret_cast<float*>(smem);
        const float bias = (EPI == EPI_ATT) ? biasPtr[0] : 0.f;
        const float* mRow = g_scratch + OFF_MASK1 + (long)b * Sn;
        const float* mCol = g_scratch + OFF_MASK2 + (long)b * Sn;
#pragma unroll
        for (int mi = 0; mi < 4; mi++) {
            int r0 = wm * 64 + mi * 16 + trow;
#pragma unroll
            for (int ni = 0; ni < 4; ni++) {
                int c0 = wn * 32 + ni * 8 + tcol;
                float v0 = acc[mi][ni][0], v1 = acc[mi][ni][1];
                float v2 = acc[mi][ni][2], v3 = acc[mi][ni][3];
                if (EPI == EPI_ATT) {
                    v0 += (abs(r0 - c0) >= 10) ? bias : 0.f;
                    v1 += (abs(r0 - c0 - 1) >= 10) ? bias : 0.f;
                    v2 += (abs(r0 + 8 - c0) >= 10) ? bias : 0.f;
                    v3 += (abs(r0 + 8 - c0 - 1) >= 10) ? bias : 0.f;
                } else {
                    float rm0 = mRow[r0], rm1 = mRow[r0 + 8];
                    float cm0 = mCol[c0], cm1 = mCol[c0 + 1];
                    v0 *= rm0 * cm0; v1 *= rm0 * cm1;
                    v2 *= rm1 * cm0; v3 *= rm1 * cm1;
                }
                smF[r0 * 129 + c0] = v0;
                smF[r0 * 129 + c0 + 1] = v1;
                smF[(r0 + 8) * 129 + c0] = v2;
                smF[(r0 + 8) * 129 + c0 + 1] = v3;
            }
        }
        __syncthreads();
        // row softmax: warp per row, 16 rows per warp
        {
            __nv_bfloat16* Chi = g_act + offC + (long)b * sC;
            __nv_bfloat16* Clo = Chi + planeC;
            for (int r = wid; r < 128; r += 8) {
                float v[4];
                float mx = -1e30f;
#pragma unroll
                for (int k = 0; k < 4; k++) {
                    v[k] = smF[r * 129 + lane + k * 32];
                    mx = fmaxf(mx, v[k]);
                }
#pragma unroll
                for (int o = 16; o; o >>= 1) mx = fmaxf(mx, __shfl_xor_sync(0xffffffffu, mx, o));
                float s = 0.f;
#pragma unroll
                for (int k = 0; k < 4; k++) {
                    v[k] = expf(v[k] - mx);
                    s += v[k];
                }
#pragma unroll
                for (int o = 16; o; o >>= 1) s += __shfl_xor_sync(0xffffffffu, s, o);
                float inv = 1.0f / s;
#pragma unroll
                for (int k = 0; k < 4; k++) {
                    __nv_bfloat16 h, l;
                    split1(v[k] * inv, h, l);
                    long e = (long)r * Sn + lane + k * 32;
                    Chi[e] = h;
                    Clo[e] = l;
                }
            }
        }
        if constexpr (EPI == EPI_SIM) {
            // col softmax written transposed: out2[c][r]
            __nv_bfloat16* C2hi = g_act + offC2 + (long)b * sC;
            __nv_bfloat16* C2lo = C2hi + planeC2;
            for (int c = wid; c < 128; c += 8) {
                float v[4];
                float mx = -1e30f;
#pragma unroll
                for (int k = 0; k < 4; k++) {
                    v[k] = smF[(lane + k * 32) * 129 + c];
                    mx = fmaxf(mx, v[k]);
                }
#pragma unroll
                for (int o = 16; o; o >>= 1) mx = fmaxf(mx, __shfl_xor_sync(0xffffffffu, mx, o));
                float s = 0.f;
#pragma unroll
                for (int k = 0; k < 4; k++) {
                    v[k] = expf(v[k] - mx);
                    s += v[k];
                }
#pragma unroll
                for (int o = 16; o; o >>= 1) s += __shfl_xor_sync(0xffffffffu, s, o);
                float inv = 1.0f / s;
#pragma unroll
                for (int k = 0; k < 4; k++) {
                    __nv_bfloat16 h, l;
                    split1(v[k] * inv, h, l);
                    long e = (long)c * Sn + lane + k * 32;
                    C2hi[e] = h;
                    C2lo[e] = l;
                }
            }
        }
    } else {  // EPI_POOL: relu + masked row-sum -> g_scratch pool
        const int side = blockIdx.z;
        const float* mask = g_scratch + (side ? OFF_MASK2 : OFF_MASK1) + (long)blockIdx.y * Sn;
        float* smP = reinterpret_cast<float*>(smem);  // [2][128]
        float p[4][2];
#pragma unroll
        for (int ni = 0; ni < 4; ni++) { p[ni][0] = 0.f; p[ni][1] = 0.f; }
#pragma unroll
        for (int mi = 0; mi < 4; mi++) {
            int r0 = wm * 64 + mi * 16 + trow;
            float m0v = mask[r0], m1v = mask[r0 + 8];
#pragma unroll
            for (int ni = 0; ni < 4; ni++) {
                p[ni][0] += fmaxf(acc[mi][ni][0], 0.f) * m0v + fmaxf(acc[mi][ni][2], 0.f) * m1v;
                p[ni][1] += fmaxf(acc[mi][ni][1], 0.f) * m0v + fmaxf(acc[mi][ni][3], 0.f) * m1v;
            }
        }
        // reduce over trow (lanes xor 4,8,16)
#pragma unroll
        for (int ni = 0; ni < 4; ni++) {
#pragma unroll
            for (int o = 4; o <= 16; o <<= 1) {
                p[ni][0] += __shfl_xor_sync(0xffffffffu, p[ni][0], o);
                p[ni][1] += __shfl_xor_sync(0xffffffffu, p[ni][1], o);
            }
        }
        __syncthreads();  // staging smem fully dead
        if (lane < 4) {
#pragma unroll
            for (int ni = 0; ni < 4; ni++) {
                smP[wm * 128 + wn * 32 + ni * 8 + lane * 2] = p[ni][0];
                smP[wm * 128 + wn * 32 + ni * 8 + lane * 2 + 1] = p[ni][1];
            }
        }
        __syncthreads();
        if (tid < 128) {
            int gcol = n0 + tid;
            if (gcol < Nreal) {
                g_scratch[OFF_POOL + (long)blockIdx.y * 800 + (long)side * 400 + gcol] =
                    smP[tid] + smP[128 + tid];
            }
        }
    }
}

// ---------------------------------------------------------------------------
// All weights: transpose + split, one launch. W [K][N] f32 -> [N][Kp] hi/lo
// ---------------------------------------------------------------------------
__global__ void k_wsplit_all(const float* __restrict__ w_intra,
                             const float* __restrict__ w_proj1,
                             const float* __restrict__ w_proj2,
                             const float* __restrict__ w_att,
                             const float* __restrict__ w_cmp1,
                             const float* __restrict__ w_cmp2) {
    const float* W;
    int K, N, Kp;
    long off;
    switch (blockIdx.y) {
        case 0: W = w_intra; K = En;     N = En;     Kp = EP;     off = WT_INTRA; break;
        case 1: W = w_proj1; K = 2 * En; N = Pn;     Kp = 2 * En; off = WT_PROJ1; break;
        case 2: W = w_proj2; K = 2 * En; N = Pn;     Kp = 2 * En; off = WT_PROJ2; break;
        case 3: W = w_att;   K = Pn;     N = Pn;     Kp = Pn;     off = WT_ATT;   break;
        case 4: W = w_cmp1;  K = 2 * Pn; N = 2 * Pn; Kp = 2 * Pn; off = WT_CMP1;  break;
        default: W = w_cmp2; K = 2 * Pn; N = 2 * Pn; Kp = 2 * Pn; off = WT_CMP2;  break;
    }
    long total = (long)K * N;
    long plane = (long)N * Kp;
    for (long i = (long)blockIdx.x * blockDim.x + threadIdx.x; i < total;
         i += (long)gridDim.x * blockDim.x) {
        int n = (int)(i / K), k = (int)(i % K);
        float v = W[(long)k * N + n];
        __nv_bfloat16 h, l;
        split1(v, h, l);
        g_wt[off + (long)n * Kp + k] = h;
        g_wt[off + plane + (long)n * Kp + k] = l;
    }
}

// ---------------------------------------------------------------------------
// Non-GEMM kernels
// ---------------------------------------------------------------------------
__global__ void k_seqmask(const int* __restrict__ x1, const int* __restrict__ x2) {
    int b = blockIdx.x;
    const int* x = blockIdx.y ? x2 : x1;
    float* m = g_scratch + (blockIdx.y ? OFF_MASK2 : OFF_MASK1);
    int t = threadIdx.x;
    int nz = __syncthreads_count(x[b * Sn + t] != 0);
    m[b * Sn + t] = (t < nz) ? 1.0f : 0.0f;
}

__global__ void k_gather(const int* __restrict__ x1, const int* __restrict__ x2,
                         const float* __restrict__ emb) {
    long bs = blockIdx.x;
    int side = blockIdx.y;
    const int* x = side ? x2 : x1;
    int row = x[bs];
    const float* e = emb + (long)row * En;
    int t = threadIdx.x;
    float v[3];
    float ss = 0.f;
#pragma unroll
    for (int i = 0; i < 3; i++) {
        int idx = t + i * 128;
        v[i] = (idx < En) ? e[idx] : 0.f;
        ss += v[i] * v[i];
    }
    __shared__ float red[4];
#pragma unroll
    for (int o = 16; o; o >>= 1) ss += __shfl_xor_sync(0xffffffffu, ss, o);
    if ((t & 31) == 0) red[t >> 5] = ss;
    __syncthreads();
    float inv = 1.0f / sqrtf(fmaxf(red[0] + red[1] + red[2] + red[3], 1e-12f));
    __nv_bfloat16* hi = g_act + ACT_CAT + (long)side * BS * 600 + bs * 600;
    __nv_bfloat16* lo = hi + CAT_PL;
#pragma unroll
    for (int i = 0; i < 3; i++) {
        int idx = t + i * 128;
        if (idx < En) {
            __nv_bfloat16 h, l;
            split1(v[i] * inv, h, l);
            hi[idx] = h;
            lo[idx] = l;
        }
    }
}

__global__ void k_final(const float* __restrict__ w_agg, float* __restrict__ out) {
    int b = blockIdx.x;
    int tid = threadIdx.x;
    int c = tid >> 5, lane = tid & 31;
    const float* p = g_scratch + OFF_POOL + (long)b * 800;
    float acc = 0.f;
    for (int n = lane; n < 800; n += 32) acc += p[n] * w_agg[n * Cn + c];
#pragma unroll
    for (int o = 16; o; o >>= 1) acc += __shfl_xor_sync(0xffffffffu, acc, o);
    if (lane == 0) out[b * Cn + c] = fmaxf(acc, 0.f);
}

// ---------------------------------------------------------------------------
// Orchestration
// ---------------------------------------------------------------------------
template <int EPI>
static inline void launch_gemm(long offA, int lda, long sA, long planeA,
                               int bMode, long offB, int ldb, long sB, long planeB,
                               long offC, int ldc, long sC, long planeC,
                               long offC2, long planeC2,
                               int M, int Nreal, int K, int doRelu,
                               const float* biasPtr, int batch) {
    dim3 grid((Nreal + 127) / 128, M / 128, batch);
    k_hmma_gemm<EPI><<<grid, 256, SMEM_BYTES>>>(offA, lda, sA, planeA,
                                                bMode, offB, ldb, sB, planeB,
                                                offC, ldc, sC, planeC,
                                                offC2, planeC2,
                                                Nreal, K, doRelu, biasPtr);
}

extern "C" void kernel_launch(void* const* d_in, const int* in_sizes, int n_in,
                              void* d_out, int out_size) {
    const int* x1 = (const int*)d_in[0];
    const int* x2 = (const int*)d_in[1];
    const float* emb = (const float*)d_in[2];
    const float* w_intra = (const float*)d_in[3];
    const float* bias_intra = (const float*)d_in[4];
    const float* w_proj1 = (const float*)d_in[5];
    const float* w_proj2 = (const float*)d_in[6];
    const float* w_att = (const float*)d_in[7];
    const float* w_cmp1 = (const float*)d_in[8];
    const float* w_cmp2 = (const float*)d_in[9];
    const float* w_agg = (const float*)d_in[10];
    float* out = (float*)d_out;

    cudaFuncSetAttribute(k_hmma_gemm<EPI_STORE>, cudaFuncAttributeMaxDynamicSharedMemorySize, SMEM_BYTES);
    cudaFuncSetAttribute(k_hmma_gemm<EPI_ATT>, cudaFuncAttributeMaxDynamicSharedMemorySize, SMEM_BYTES);
    cudaFuncSetAttribute(k_hmma_gemm<EPI_SIM>, cudaFuncAttributeMaxDynamicSharedMemorySize, SMEM_BYTES);
    cudaFuncSetAttribute(k_hmma_gemm<EPI_POOL>, cudaFuncAttributeMaxDynamicSharedMemorySize, SMEM_BYTES);

    k_seqmask<<<dim3(Bn, 2), Sn>>>(x1, x2);
    k_gather<<<dim3((unsigned)BS, 2), 128>>>(x1, x2, emb);
    k_wsplit_all<<<dim3(160, 6), 256>>>(w_intra, w_proj1, w_proj2, w_att, w_cmp1, w_cmp2);

    // f = relu(e @ w_intra), both sides: [2 x BS x 300], K=300
    launch_gemm<EPI_STORE>(ACT_CAT, 600, BS * 600, CAT_PL,
                           0, WT_INTRA, EP, 0, 300L * EP,
                           ACT_F, EP, BS * EP, F_PL, 0, 0,
                           (int)BS, En, En, 1, nullptr, 2);

    // att = softmax_rows(f@f^T + dbias), fused: 512 batches
    launch_gemm<EPI_ATT>(ACT_F, EP, (long)Sn * EP, F_PL,
                         1, ACT_F, EP, (long)Sn * EP, F_PL,
                         ACT_ATT, Sn, (long)Sn * Sn, ATT_PL, 0, 0,
                         Sn, Sn, En, 0, bias_intra, 2 * Bn);

    // xp[g] = att[g] @ e[g]: B N-major from cat cols 0:300 -> cat cols 300:600
    launch_gemm<EPI_STORE>(ACT_ATT, Sn, (long)Sn * Sn, ATT_PL,
                           2, ACT_CAT, 600, (long)Sn * 600, CAT_PL,
                           ACT_CAT + En, 600, (long)Sn * 600, CAT_PL, 0, 0,
                           Sn, En, Sn, 0, nullptr, 2 * Bn);

    // x_proj = relu(cat @ w_proj{1,2}): [2 x BS x 200], K=600
    launch_gemm<EPI_STORE>(ACT_CAT, 600, BS * 600, CAT_PL,
                           0, WT_PROJ1, 600, WT_PROJ2 - WT_PROJ1, 120000,
                           ACT_CATP, 400, BS * 400, CATP_PL, 0, 0,
                           (int)BS, Pn, 2 * En, 1, nullptr, 2);

    // fa = relu(x_proj @ w_att): [2 x BS x 200], K=200
    launch_gemm<EPI_STORE>(ACT_CATP, 400, BS * 400, CATP_PL,
                           0, WT_ATT, Pn, 0, 40000,
                           ACT_FA, Pn, BS * Pn, FA_PL, 0, 0,
                           (int)BS, Pn, Pn, 1, nullptr, 2);

    // sim: fused mask + row softmax (-> SIM) + col softmax^T (-> SMT)
    launch_gemm<EPI_SIM>(ACT_FA, Pn, (long)Sn * Pn, FA_PL,
                         1, ACT_FA + BS * Pn, Pn, (long)Sn * Pn, FA_PL,
                         ACT_SIM, Sn, (long)Sn * Sn, SIM_PL,
                         ACT_SMT, SMT_PL,
                         Sn, Sn, Pn, 0, nullptr, Bn);

    // beta[b] = sm2[b] @ x2p[b] -> cat1p cols 200:400
    launch_gemm<EPI_STORE>(ACT_SIM, Sn, (long)Sn * Sn, SIM_PL,
                           2, ACT_CATP + BS * 400, 400, (long)Sn * 400, CATP_PL,
                           ACT_CATP + Pn, 400, (long)Sn * 400, CATP_PL, 0, 0,
                           Sn, Pn, Sn, 0, nullptr, Bn);

    // alpha[b] = smT[b] @ x1p[b] -> cat2p cols 200:400
    launch_gemm<EPI_STORE>(ACT_SMT, Sn, (long)Sn * Sn, SMT_PL,
                           2, ACT_CATP, 400, (long)Sn * 400, CATP_PL,
                           ACT_CATP + BS * 400 + Pn, 400, (long)Sn * 400, CATP_PL, 0, 0,
                           Sn, Pn, Sn, 0, nullptr, Bn);

    // v = relu([xp|attend] @ w_cmp{1,2}) fused with masked-sum pooling
    // grid: (4 n-tiles, 256 batches, 2 sides)
    launch_gemm<EPI_POOL>(ACT_CATP, 400, BS * 400, CATP_PL,
                          0, WT_CMP1, 2 * Pn, WT_CMP2 - WT_CMP1, 160000,
                          0, 0, 0, 0, 0, 0,
                          (int)BS, 2 * Pn, 2 * Pn, 1, nullptr, 2);

    k_final<<<Bn, 96>>>(w_agg, out);
}

// round 7
// speedup vs baseline: 1.1561x; 1.0019x over previous
#include <cuda_runtime.h>
#include <cuda_bf16.h>
#include <math.h>
#include <stdint.h>

// ---------------------------------------------------------------------------
// Problem constants
// ---------------------------------------------------------------------------
namespace {
constexpr int Bn = 256, Sn = 128, En = 300, Pn = 200, Cn = 3;
constexpr long BS = (long)Bn * Sn;  // 32768
constexpr int EP = 304;             // 300 padded to 16B multiple

// ---- f32 scratch (masks + pool)
constexpr long OFF_MASK1 = 0;
constexpr long OFF_MASK2 = OFF_MASK1 + BS;
constexpr long OFF_POOL  = OFF_MASK2 + BS;
constexpr long F32_TOTAL = OFF_POOL + (long)Bn * 4 * Pn;

// ---- bf16 activation arena: every tensor is two planes (hi, lo = +PLANE)
constexpr long ACT_CAT  = 0;                        // [2][BS][600]
constexpr long CAT_PL   = 2 * BS * 600;
constexpr long ACT_F    = ACT_CAT + 2 * CAT_PL;     // [2*BS][304]
constexpr long F_PL     = 2 * BS * EP;
constexpr long ACT_ATT  = ACT_F + 2 * F_PL;         // [2*B][S][S] (softmaxed)
constexpr long ATT_PL   = 2 * BS * Sn;
constexpr long ACT_CATP = ACT_ATT + 2 * ATT_PL;     // [2][BS][400]
constexpr long CATP_PL  = 2 * BS * 2 * Pn;
constexpr long ACT_FA   = ACT_CATP + 2 * CATP_PL;   // [2][BS][200]
constexpr long FA_PL    = 2 * BS * Pn;
constexpr long ACT_SIM  = ACT_FA + 2 * FA_PL;       // [B][S][S] row-softmaxed
constexpr long SIM_PL   = BS * Sn;
constexpr long ACT_SMT  = ACT_SIM + 2 * SIM_PL;     // [B][S][S] col-softmax^T
constexpr long SMT_PL   = BS * Sn;
constexpr long ACT_TOTAL = ACT_SMT + 2 * SMT_PL;

// ---- split weights, bf16 [N][Kpad]; lo plane at +N*Kpad
constexpr long WT_INTRA = 0;                          // 300 x 304
constexpr long WT_PROJ1 = WT_INTRA + 2L * 300 * EP;   // 200 x 600
constexpr long WT_PROJ2 = WT_PROJ1 + 2L * 120000;
constexpr long WT_ATT   = WT_PROJ2 + 2L * 120000;     // 200 x 200
constexpr long WT_CMP1  = WT_ATT + 2L * 40000;        // 400 x 400
constexpr long WT_CMP2  = WT_CMP1 + 2L * 160000;
constexpr long WT_TOTAL = WT_CMP2 + 2L * 160000;

// staging smem (bytes): rows padded to 80B for conflict-free ldmatrix
constexpr int SM_AH = 0;
constexpr int SM_AL = 10240;
constexpr int SM_BH = 20480;
constexpr int SM_BL = 30720;
constexpr int SM_BUF = 40960;
constexpr int SMEM_BYTES = 2 * SM_BUF;  // 80 KB (also covers 128x129 f32)

enum { EPI_STORE = 0, EPI_ATT = 1, EPI_SIM = 2, EPI_POOL = 3 };
}  // namespace

__device__ float g_scratch[F32_TOTAL];
__device__ __nv_bfloat16 g_act[ACT_TOTAL];
__device__ __nv_bfloat16 g_wt[WT_TOTAL];

// ---------------------------------------------------------------------------
// helpers
// ---------------------------------------------------------------------------
__device__ __forceinline__ uint32_t smem_u32(const void* p) {
    uint32_t a;
    asm("{ .reg .u64 t; cvta.to.shared.u64 t, %1; cvt.u32.u64 %0, t; }" : "=r"(a) : "l"(p));
    return a;
}
__device__ __forceinline__ void split1(float v, __nv_bfloat16& h, __nv_bfloat16& l) {
    h = __float2bfloat16(v);
    l = __float2bfloat16(v - __bfloat162float(h));
}
__device__ __forceinline__ void cp16(uint32_t dst, const void* src, int bytes) {
    asm volatile("cp.async.cg.shared.global [%0], [%1], 16, %2;"
                 :: "r"(dst), "l"(src), "r"(bytes) : "memory");
}
__device__ __forceinline__ void cp_commit() {
    asm volatile("cp.async.commit_group;" ::: "memory");
}
template <int N>
__device__ __forceinline__ void cp_wait() {
    asm volatile("cp.async.wait_group %0;" :: "n"(N) : "memory");
}
__device__ __forceinline__ void ldm_x4(uint32_t* r, uint32_t addr) {
    asm volatile("ldmatrix.sync.aligned.m8n8.x4.shared.b16 {%0,%1,%2,%3}, [%4];"
                 : "=r"(r[0]), "=r"(r[1]), "=r"(r[2]), "=r"(r[3]) : "r"(addr));
}
__device__ __forceinline__ void ldm_x2(uint32_t* r, uint32_t addr) {
    asm volatile("ldmatrix.sync.aligned.m8n8.x2.shared.b16 {%0,%1}, [%2];"
                 : "=r"(r[0]), "=r"(r[1]) : "r"(addr));
}
__device__ __forceinline__ void mma16816(float* c, const uint32_t* a, const uint32_t* b) {
    asm volatile(
        "mma.sync.aligned.m16n8k16.row.col.f32.bf16.bf16.f32 "
        "{%0,%1,%2,%3}, {%4,%5,%6,%7}, {%8,%9}, {%0,%1,%2,%3};"
        : "+f"(c[0]), "+f"(c[1]), "+f"(c[2]), "+f"(c[3])
        : "r"(a[0]), "r"(a[1]), "r"(a[2]), "r"(a[3]), "r"(b[0]), "r"(b[1]));
}

// ---------------------------------------------------------------------------
// Pipelined HMMA GEMM on pre-split bf16 hi/lo planes (3 MMAs / k-step),
// with fused epilogues:
//   EPI_STORE: (+relu) -> hi/lo planes at offC
//   EPI_ATT:   +dbias, row softmax (in-CTA over 128x128) -> planes at offC
//   EPI_SIM:   x mask1[r]*mask2[c], row softmax -> offC, col softmax^T -> offC2
//   EPI_POOL:  relu, masked sum over rows -> f32 pool (g_scratch)
// bMode: 0 = B from g_wt ([N][ldb] k-contig), 1 = B from g_act (k-contig),
//        2 = B from g_act N-major ([K][ldb], transpose-staged)
// ---------------------------------------------------------------------------
template <int EPI>
__global__ void __launch_bounds__(256, 2)
k_hmma_gemm(long offA, int lda, long sA, long planeA,
            int bMode, long offB, int ldb, long sB, long planeB,
            long offC, int ldc, long sC, long planeC,
            long offC2, long planeC2,
            int Nreal, int K, int doRelu, const float* biasPtr) {
    extern __shared__ __align__(16) char smem[];
    const uint32_t sb0 = smem_u32(smem);
    const int tid = threadIdx.x;
    const int lane = tid & 31, wid = tid >> 5;
    const int wm = wid & 1, wn = wid >> 1;  // 2x4 warp grid -> 64x32 per warp
    const int n0 = blockIdx.x * 128, m0 = blockIdx.y * 128, b = blockIdx.z;

    const __nv_bfloat16* Ahi = g_act + offA + (long)b * sA;
    const __nv_bfloat16* Alo = Ahi + planeA;
    const __nv_bfloat16* Bhi = (bMode == 0 ? g_wt : g_act) + offB + (long)b * sB;
    const __nv_bfloat16* Blo = Bhi + planeB;

    float acc[4][4][4] = {};
    const int crow = tid >> 2, cch = tid & 3;
    const int nN = (tid & 63) * 2, nKb = tid >> 6;
    const int nChunks = (K + 31) >> 5;
    uint32_t pfh[8], pfl[8];

#define ISSUE_A(c, bi)                                                          \
    {                                                                           \
        const int k0 = (c) << 5;                                                \
        _Pragma("unroll") for (int i = 0; i < 2; i++) {                         \
            int row = crow + i * 64;                                            \
            int gk = k0 + cch * 8;                                              \
            int bytes = K - gk;                                                 \
            bytes = bytes < 0 ? 0 : (bytes > 8 ? 8 : bytes);                    \
            bytes *= 2;                                                         \
            long ro = (long)(m0 + row) * lda;                                   \
            uint32_t d = sb0 + (bi)*SM_BUF + (uint32_t)(row * 80 + cch * 16);   \
            cp16(d + SM_AH, Ahi + ro + (bytes ? gk : 0), bytes);                \
            cp16(d + SM_AL, Alo + ro + (bytes ? gk : 0), bytes);                \
        }                                                                       \
    }
#define ISSUE_B(c, bi)                                                          \
    {                                                                           \
        const int k0 = (c) << 5;                                                \
        _Pragma("unroll") for (int i = 0; i < 2; i++) {                         \
            int n = crow + i * 64;                                              \
            int gn = n0 + n;                                                    \
            int gk = k0 + cch * 8;                                              \
            int bytes = K - gk;                                                 \
            bytes = bytes < 0 ? 0 : (bytes > 8 ? 8 : bytes);                    \
            bytes *= 2;                                                         \
            if (gn >= Nreal) bytes = 0;                                         \
            long ro = bytes ? (long)gn * ldb + gk : 0;                          \
            uint32_t d = sb0 + (bi)*SM_BUF + (uint32_t)(n * 80 + cch * 16);     \
            cp16(d + SM_BH, Bhi + ro, bytes);                                   \
            cp16(d + SM_BL, Blo + ro, bytes);                                   \
        }                                                                       \
    }
#define LDGB(c)                                                                 \
    {                                                                           \
        const int k0 = (c) << 5;                                                \
        const int gn = n0 + nN;                                                 \
        const bool nin = (gn < Nreal);                                          \
        _Pragma("unroll") for (int it = 0; it < 8; it++) {                      \
            int gk = k0 + nKb + it * 4;                                         \
            if (nin && gk < K) {                                                \
                long e = (long)gk * ldb + gn;                                   \
                pfh[it] = *reinterpret_cast<const uint32_t*>(Bhi + e);          \
                pfl[it] = *reinterpret_cast<const uint32_t*>(Blo + e);          \
            } else {                                                            \
                pfh[it] = 0; pfl[it] = 0;                                       \
            }                                                                   \
        }                                                                       \
    }
#define STOREB(bi)                                                              \
    {                                                                           \
        char* sm = smem + (bi)*SM_BUF;                                          \
        _Pragma("unroll") for (int it = 0; it < 8; it++) {                      \
            int kk = nKb + it * 4;                                              \
            __nv_bfloat162 h2 = *reinterpret_cast<__nv_bfloat162*>(&pfh[it]);   \
            __nv_bfloat162 l2 = *reinterpret_cast<__nv_bfloat162*>(&pfl[it]);   \
            *reinterpret_cast<__nv_bfloat16*>(sm + SM_BH + nN * 80 + kk * 2) = h2.x; \
            *reinterpret_cast<__nv_bfloat16*>(sm + SM_BL + nN * 80 + kk * 2) = l2.x; \
            *reinterpret_cast<__nv_bfloat16*>(sm + SM_BH + (nN + 1) * 80 + kk * 2) = h2.y; \
            *reinterpret_cast<__nv_bfloat16*>(sm + SM_BL + (nN + 1) * 80 + kk * 2) = l2.y; \
        }                                                                       \
    }

    ISSUE_A(0, 0);
    if (bMode < 2) { ISSUE_B(0, 0); } else { LDGB(0); }
    cp_commit();
    if (bMode == 2) STOREB(0);

    for (int c = 0; c < nChunks; c++) {
        const bool more = (c + 1 < nChunks);
        if (more) {
            ISSUE_A(c + 1, (c + 1) & 1);
            if (bMode < 2) ISSUE_B(c + 1, (c + 1) & 1);
            cp_commit();
            if (bMode == 2) LDGB(c + 1);
        }
        if (more) cp_wait<1>(); else cp_wait<0>();
        __syncthreads();

        const uint32_t sb = sb0 + (uint32_t)((c & 1) * SM_BUF);
#pragma unroll
        for (int ks = 0; ks < 2; ks++) {
            uint32_t bh[4][2], bl[4][2];
#pragma unroll
            for (int ni = 0; ni < 4; ni++) {
                uint32_t off = (uint32_t)((wn * 32 + ni * 8 + (lane & 7)) * 80 + ks * 32 +
                                          ((lane >> 3) & 1) * 16);
                ldm_x2(bh[ni], sb + SM_BH + off);
                ldm_x2(bl[ni], sb + SM_BL + off);
            }
#pragma unroll
            for (int mi = 0; mi < 4; mi++) {
                uint32_t ah[4], al[4];
                uint32_t off = (uint32_t)((wm * 64 + mi * 16 + (lane & 15)) * 80 + ks * 32 +
                                          (lane >> 4) * 16);
                ldm_x4(ah, sb + SM_AH + off);
                ldm_x4(al, sb + SM_AL + off);
#pragma unroll
                for (int ni = 0; ni < 4; ni++) {
                    mma16816(acc[mi][ni], ah, bh[ni]);
                    mma16816(acc[mi][ni], ah, bl[ni]);
                    mma16816(acc[mi][ni], al, bh[ni]);
                }
            }
        }
        if (bMode == 2 && more) STOREB((c + 1) & 1);
        __syncthreads();
    }
#undef ISSUE_A
#undef ISSUE_B
#undef LDGB
#undef STOREB

    const int trow = lane >> 2, tcol = (lane & 3) * 2;

    if constexpr (EPI == EPI_STORE) {
        __nv_bfloat16* Chi = g_act + offC + (long)b * sC;
        __nv_bfloat16* Clo = Chi + planeC;
#pragma unroll
        for (int mi = 0; mi < 4; mi++) {
            int r0 = m0 + wm * 64 + mi * 16 + trow;
#pragma unroll
            for (int ni = 0; ni < 4; ni++) {
                int c0 = n0 + wn * 32 + ni * 8 + tcol;
                if (c0 >= Nreal) continue;
                float v0 = acc[mi][ni][0], v1 = acc[mi][ni][1];
                float v2 = acc[mi][ni][2], v3 = acc[mi][ni][3];
                if (doRelu) {
                    v0 = fmaxf(v0, 0.f); v1 = fmaxf(v1, 0.f);
                    v2 = fmaxf(v2, 0.f); v3 = fmaxf(v3, 0.f);
                }
                __nv_bfloat162 h01, l01, h23, l23;
                split1(v0, h01.x, l01.x); split1(v1, h01.y, l01.y);
                split1(v2, h23.x, l23.x); split1(v3, h23.y, l23.y);
                long e0 = (long)r0 * ldc + c0, e1 = (long)(r0 + 8) * ldc + c0;
                *reinterpret_cast<__nv_bfloat162*>(Chi + e0) = h01;
                *reinterpret_cast<__nv_bfloat162*>(Clo + e0) = l01;
                *reinterpret_cast<__nv_bfloat162*>(Chi + e1) = h23;
                *reinterpret_cast<__nv_bfloat162*>(Clo + e1) = l23;
            }
        }
    } else if constexpr (EPI == EPI_ATT || EPI == EPI_SIM) {
        // dump acc (+dbias or masks) into 128x129 f32 smem
        float* smF = reinterpret_cast<float*>(smem);
        const float bias = (EPI == EPI_ATT) ? biasPtr[0] : 0.f;
        const float* mRow = g_scratch + OFF_MASK1 + (long)b * Sn;
        const float* mCol = g_scratch + OFF_MASK2 + (long)b * Sn;
#pragma unroll
        for (int mi = 0; mi < 4; mi++) {
            int r0 = wm * 64 + mi * 16 + trow;
#pragma unroll
            for (int ni = 0; ni < 4; ni++) {
                int c0 = wn * 32 + ni * 8 + tcol;
                float v0 = acc[mi][ni][0], v1 = acc[mi][ni][1];
                float v2 = acc[mi][ni][2], v3 = acc[mi][ni][3];
                if (EPI == EPI_ATT) {
                    v0 += (abs(r0 - c0) >= 10) ? bias : 0.f;
                    v1 += (abs(r0 - c0 - 1) >= 10) ? bias : 0.f;
                    v2 += (abs(r0 + 8 - c0) >= 10) ? bias : 0.f;
                    v3 += (abs(r0 + 8 - c0 - 1) >= 10) ? bias : 0.f;
                } else {
                    float rm0 = mRow[r0], rm1 = mRow[r0 + 8];
                    float cm0 = mCol[c0], cm1 = mCol[c0 + 1];
                    v0 *= rm0 * cm0; v1 *= rm0 * cm1;
                    v2 *= rm1 * cm0; v3 *= rm1 * cm1;
                }
                smF[r0 * 129 + c0] = v0;
                smF[r0 * 129 + c0 + 1] = v1;
                smF[(r0 + 8) * 129 + c0] = v2;
                smF[(r0 + 8) * 129 + c0 + 1] = v3;
            }
        }
        __syncthreads();
        // row softmax: warp per row, 16 rows per warp
        {
            __nv_bfloat16* Chi = g_act + offC + (long)b * sC;
            __nv_bfloat16* Clo = Chi + planeC;
            for (int r = wid; r < 128; r += 8) {
                float v[4];
                float mx = -1e30f;
#pragma unroll
                for (int k = 0; k < 4; k++) {
                    v[k] = smF[r * 129 + lane + k * 32];
                    mx = fmaxf(mx, v[k]);
                }
#pragma unroll
                for (int o = 16; o; o >>= 1) mx = fmaxf(mx, __shfl_xor_sync(0xffffffffu, mx, o));
                float s = 0.f;
#pragma unroll
                for (int k = 0; k < 4; k++) {
                    v[k] = expf(v[k] - mx);
                    s += v[k];
                }
#pragma unroll
                for (int o = 16; o; o >>= 1) s += __shfl_xor_sync(0xffffffffu, s, o);
                float inv = 1.0f / s;
#pragma unroll
                for (int k = 0; k < 4; k++) {
                    __nv_bfloat16 h, l;
                    split1(v[k] * inv, h, l);
                    long e = (long)r * Sn + lane + k * 32;
                    Chi[e] = h;
                    Clo[e] = l;
                }
            }
        }
        if constexpr (EPI == EPI_SIM) {
            // col softmax written transposed: out2[c][r]
            __nv_bfloat16* C2hi = g_act + offC2 + (long)b * sC;
            __nv_bfloat16* C2lo = C2hi + planeC2;
            for (int c = wid; c < 128; c += 8) {
                float v[4];
                float mx = -1e30f;
#pragma unroll
                for (int k = 0; k < 4; k++) {
                    v[k] = smF[(lane + k * 32) * 129 + c];
                    mx = fmaxf(mx, v[k]);
                }
#pragma unroll
                for (int o = 16; o; o >>= 1) mx = fmaxf(mx, __shfl_xor_sync(0xffffffffu, mx, o));
                float s = 0.f;
#pragma unroll
                for (int k = 0; k < 4; k++) {
                    v[k] = expf(v[k] - mx);
                    s += v[k];
                }
#pragma unroll
                for (int o = 16; o; o >>= 1) s += __shfl_xor_sync(0xffffffffu, s, o);
                float inv = 1.0f / s;
#pragma unroll
                for (int k = 0; k < 4; k++) {
                    __nv_bfloat16 h, l;
                    split1(v[k] * inv, h, l);
                    long e = (long)c * Sn + lane + k * 32;
                    C2hi[e] = h;
                    C2lo[e] = l;
                }
            }
        }
    } else {  // EPI_POOL: relu + masked row-sum -> g_scratch pool
        const int side = blockIdx.z;
        const float* mask = g_scratch + (side ? OFF_MASK2 : OFF_MASK1) + (long)blockIdx.y * Sn;
        float* smP = reinterpret_cast<float*>(smem);  // [2][128]
        float p[4][2];
#pragma unroll
        for (int ni = 0; ni < 4; ni++) { p[ni][0] = 0.f; p[ni][1] = 0.f; }
#pragma unroll
        for (int mi = 0; mi < 4; mi++) {
            int r0 = wm * 64 + mi * 16 + trow;
            float m0v = mask[r0], m1v = mask[r0 + 8];
#pragma unroll
            for (int ni = 0; ni < 4; ni++) {
                p[ni][0] += fmaxf(acc[mi][ni][0], 0.f) * m0v + fmaxf(acc[mi][ni][2], 0.f) * m1v;
                p[ni][1] += fmaxf(acc[mi][ni][1], 0.f) * m0v + fmaxf(acc[mi][ni][3], 0.f) * m1v;
            }
        }
        // reduce over trow (lanes xor 4,8,16)
#pragma unroll
        for (int ni = 0; ni < 4; ni++) {
#pragma unroll
            for (int o = 4; o <= 16; o <<= 1) {
                p[ni][0] += __shfl_xor_sync(0xffffffffu, p[ni][0], o);
                p[ni][1] += __shfl_xor_sync(0xffffffffu, p[ni][1], o);
            }
        }
        __syncthreads();  // staging smem fully dead
        if (lane < 4) {
#pragma unroll
            for (int ni = 0; ni < 4; ni++) {
                smP[wm * 128 + wn * 32 + ni * 8 + lane * 2] = p[ni][0];
                smP[wm * 128 + wn * 32 + ni * 8 + lane * 2 + 1] = p[ni][1];
            }
        }
        __syncthreads();
        if (tid < 128) {
            int gcol = n0 + tid;
            if (gcol < Nreal) {
                g_scratch[OFF_POOL + (long)blockIdx.y * 800 + (long)side * 400 + gcol] =
                    smP[tid] + smP[128 + tid];
            }
        }
    }
}

// ---------------------------------------------------------------------------
// All weights: transpose + split, one launch. W [K][N] f32 -> [N][Kp] hi/lo
// ---------------------------------------------------------------------------
__global__ void k_wsplit_all(const float* __restrict__ w_intra,
                             const float* __restrict__ w_proj1,
                             const float* __restrict__ w_proj2,
                             const float* __restrict__ w_att,
                             const float* __restrict__ w_cmp1,
                             const float* __restrict__ w_cmp2) {
    const float* W;
    int K, N, Kp;
    long off;
    switch (blockIdx.y) {
        case 0: W = w_intra; K = En;     N = En;     Kp = EP;     off = WT_INTRA; break;
        case 1: W = w_proj1; K = 2 * En; N = Pn;     Kp = 2 * En; off = WT_PROJ1; break;
        case 2: W = w_proj2; K = 2 * En; N = Pn;     Kp = 2 * En; off = WT_PROJ2; break;
        case 3: W = w_att;   K = Pn;     N = Pn;     Kp = Pn;     off = WT_ATT;   break;
        case 4: W = w_cmp1;  K = 2 * Pn; N = 2 * Pn; Kp = 2 * Pn; off = WT_CMP1;  break;
        default: W = w_cmp2; K = 2 * Pn; N = 2 * Pn; Kp = 2 * Pn; off = WT_CMP2;  break;
    }
    long total = (long)K * N;
    long plane = (long)N * Kp;
    for (long i = (long)blockIdx.x * blockDim.x + threadIdx.x; i < total;
         i += (long)gridDim.x * blockDim.x) {
        int n = (int)(i / K), k = (int)(i % K);
        float v = W[(long)k * N + n];
        __nv_bfloat16 h, l;
        split1(v, h, l);
        g_wt[off + (long)n * Kp + k] = h;
        g_wt[off + plane + (long)n * Kp + k] = l;
    }
}

// ---------------------------------------------------------------------------
// Non-GEMM kernels
// ---------------------------------------------------------------------------
__global__ void k_seqmask(const int* __restrict__ x1, const int* __restrict__ x2) {
    int b = blockIdx.x;
    const int* x = blockIdx.y ? x2 : x1;
    float* m = g_scratch + (blockIdx.y ? OFF_MASK2 : OFF_MASK1);
    int t = threadIdx.x;
    int nz = __syncthreads_count(x[b * Sn + t] != 0);
    m[b * Sn + t] = (t < nz) ? 1.0f : 0.0f;
}

__global__ void k_gather(const int* __restrict__ x1, const int* __restrict__ x2,
                         const float* __restrict__ emb) {
    long bs = blockIdx.x;
    int side = blockIdx.y;
    const int* x = side ? x2 : x1;
    int row = x[bs];
    const float* e = emb + (long)row * En;
    int t = threadIdx.x;
    float v[3];
    float ss = 0.f;
#pragma unroll
    for (int i = 0; i < 3; i++) {
        int idx = t + i * 128;
        v[i] = (idx < En) ? e[idx] : 0.f;
        ss += v[i] * v[i];
    }
    __shared__ float red[4];
#pragma unroll
    for (int o = 16; o; o >>= 1) ss += __shfl_xor_sync(0xffffffffu, ss, o);
    if ((t & 31) == 0) red[t >> 5] = ss;
    __syncthreads();
    float inv = 1.0f / sqrtf(fmaxf(red[0] + red[1] + red[2] + red[3], 1e-12f));
    __nv_bfloat16* hi = g_act + ACT_CAT + (long)side * BS * 600 + bs * 600;
    __nv_bfloat16* lo = hi + CAT_PL;
#pragma unroll
    for (int i = 0; i < 3; i++) {
        int idx = t + i * 128;
        if (idx < En) {
            __nv_bfloat16 h, l;
            split1(v[i] * inv, h, l);
            hi[idx] = h;
            lo[idx] = l;
        }
    }
}

__global__ void k_final(const float* __restrict__ w_agg, float* __restrict__ out) {
    int b = blockIdx.x;
    int tid = threadIdx.x;
    int c = tid >> 5, lane = tid & 31;
    const float* p = g_scratch + OFF_POOL + (long)b * 800;
    float acc = 0.f;
    for (int n = lane; n < 800; n += 32) acc += p[n] * w_agg[n * Cn + c];
#pragma unroll
    for (int o = 16; o; o >>= 1) acc += __shfl_xor_sync(0xffffffffu, acc, o);
    if (lane == 0) out[b * Cn + c] = fmaxf(acc, 0.f);
}

// ---------------------------------------------------------------------------
// Orchestration
// ---------------------------------------------------------------------------
template <int EPI>
static inline void launch_gemm(long offA, int lda, long sA, long planeA,
                               int bMode, long offB, int ldb, long sB, long planeB,
                               long offC, int ldc, long sC, long planeC,
                               long offC2, long planeC2,
                               int M, int Nreal, int K, int doRelu,
                               const float* biasPtr, int batch) {
    dim3 grid((Nreal + 127) / 128, M / 128, batch);
    k_hmma_gemm<EPI><<<grid, 256, SMEM_BYTES>>>(offA, lda, sA, planeA,
                                                bMode, offB, ldb, sB, planeB,
                                                offC, ldc, sC, planeC,
                                                offC2, planeC2,
                                                Nreal, K, doRelu, biasPtr);
}

extern "C" void kernel_launch(void* const* d_in, const int* in_sizes, int n_in,
                              void* d_out, int out_size) {
    const int* x1 = (const int*)d_in[0];
    const int* x2 = (const int*)d_in[1];
    const float* emb = (const float*)d_in[2];
    const float* w_intra = (const float*)d_in[3];
    const float* bias_intra = (const float*)d_in[4];
    const float* w_proj1 = (const float*)d_in[5];
    const float* w_proj2 = (const float*)d_in[6];
    const float* w_att = (const float*)d_in[7];
    const float* w_cmp1 = (const float*)d_in[8];
    const float* w_cmp2 = (const float*)d_in[9];
    const float* w_agg = (const float*)d_in[10];
    float* out = (float*)d_out;

    cudaFuncSetAttribute(k_hmma_gemm<EPI_STORE>, cudaFuncAttributeMaxDynamicSharedMemorySize, SMEM_BYTES);
    cudaFuncSetAttribute(k_hmma_gemm<EPI_ATT>, cudaFuncAttributeMaxDynamicSharedMemorySize, SMEM_BYTES);
    cudaFuncSetAttribute(k_hmma_gemm<EPI_SIM>, cudaFuncAttributeMaxDynamicSharedMemorySize, SMEM_BYTES);
    cudaFuncSetAttribute(k_hmma_gemm<EPI_POOL>, cudaFuncAttributeMaxDynamicSharedMemorySize, SMEM_BYTES);

    k_seqmask<<<dim3(Bn, 2), Sn>>>(x1, x2);
    k_gather<<<dim3((unsigned)BS, 2), 128>>>(x1, x2, emb);
    k_wsplit_all<<<dim3(160, 6), 256>>>(w_intra, w_proj1, w_proj2, w_att, w_cmp1, w_cmp2);

    // f = relu(e @ w_intra), both sides: [2 x BS x 300], K=300
    launch_gemm<EPI_STORE>(ACT_CAT, 600, BS * 600, CAT_PL,
                           0, WT_INTRA, EP, 0, 300L * EP,
                           ACT_F, EP, BS * EP, F_PL, 0, 0,
                           (int)BS, En, En, 1, nullptr, 2);

    // att = softmax_rows(f@f^T + dbias), fused: 512 batches
    launch_gemm<EPI_ATT>(ACT_F, EP, (long)Sn * EP, F_PL,
                         1, ACT_F, EP, (long)Sn * EP, F_PL,
                         ACT_ATT, Sn, (long)Sn * Sn, ATT_PL, 0, 0,
                         Sn, Sn, En, 0, bias_intra, 2 * Bn);

    // xp[g] = att[g] @ e[g]: B N-major from cat cols 0:300 -> cat cols 300:600
    launch_gemm<EPI_STORE>(ACT_ATT, Sn, (long)Sn * Sn, ATT_PL,
                           2, ACT_CAT, 600, (long)Sn * 600, CAT_PL,
                           ACT_CAT + En, 600, (long)Sn * 600, CAT_PL, 0, 0,
                           Sn, En, Sn, 0, nullptr, 2 * Bn);

    // x_proj = relu(cat @ w_proj{1,2}): [2 x BS x 200], K=600
    launch_gemm<EPI_STORE>(ACT_CAT, 600, BS * 600, CAT_PL,
                           0, WT_PROJ1, 600, WT_PROJ2 - WT_PROJ1, 120000,
                           ACT_CATP, 400, BS * 400, CATP_PL, 0, 0,
                           (int)BS, Pn, 2 * En, 1, nullptr, 2);

    // fa = relu(x_proj @ w_att): [2 x BS x 200], K=200
    launch_gemm<EPI_STORE>(ACT_CATP, 400, BS * 400, CATP_PL,
                           0, WT_ATT, Pn, 0, 40000,
                           ACT_FA, Pn, BS * Pn, FA_PL, 0, 0,
                           (int)BS, Pn, Pn, 1, nullptr, 2);

    // sim: fused mask + row softmax (-> SIM) + col softmax^T (-> SMT)
    launch_gemm<EPI_SIM>(ACT_FA, Pn, (long)Sn * Pn, FA_PL,
                         1, ACT_FA + BS * Pn, Pn, (long)Sn * Pn, FA_PL,
                         ACT_SIM, Sn, (long)Sn * Sn, SIM_PL,
                         ACT_SMT, SMT_PL,
                         Sn, Sn, Pn, 0, nullptr, Bn);

    // beta[b] = sm2[b] @ x2p[b] -> cat1p cols 200:400
    launch_gemm<EPI_STORE>(ACT_SIM, Sn, (long)Sn * Sn, SIM_PL,
                           2, ACT_CATP + BS * 400, 400, (long)Sn * 400, CATP_PL,
                           ACT_CATP + Pn, 400, (long)Sn * 400, CATP_PL, 0, 0,
                           Sn, Pn, Sn, 0, nullptr, Bn);

    // alpha[b] = smT[b] @ x1p[b] -> cat2p cols 200:400
    launch_gemm<EPI_STORE>(ACT_SMT, Sn, (long)Sn * Sn, SMT_PL,
                           2, ACT_CATP, 400, (long)Sn * 400, CATP_PL,
                           ACT_CATP + BS * 400 + Pn, 400, (long)Sn * 400, CATP_PL, 0, 0,
                           Sn, Pn, Sn, 0, nullptr, Bn);

    // v = relu([xp|attend] @ w_cmp{1,2}) fused with masked-sum pooling
    // grid: (4 n-tiles, 256 batches, 2 sides)
    launch_gemm<EPI_POOL>(ACT_CATP, 400, BS * 400, CATP_PL,
                          0, WT_CMP1, 2 * Pn, WT_CMP2 - WT_CMP1, 160000,
                          0, 0, 0, 0, 0, 0,
                          (int)BS, 2 * Pn, 2 * Pn, 1, nullptr, 2);

    k_final<<<Bn, 96>>>(w_agg, out);
}